// round 2
// baseline (speedup 1.0000x reference)
#include <cuda_runtime.h>
#include <cstdint>

// Flag: 1 if voxel_num_points is int64 (little-endian, low word holds value),
// 0 if int32. Decided by probe_dtype_kernel each launch (deterministic).
__device__ int g_counts_are_i64;

// Probe: interpret counts as int64 pairs. Values are in [0,4]; if int32 data
// is misread as int64, the "high word" is a random 0..4 value -> almost surely
// nonzero somewhere in the first 32 pairs. One warp, one ballot, one store.
__global__ void probe_dtype_kernel(const int* __restrict__ counts_raw, int n_vox)
{
    int i = threadIdx.x;               // 0..31
    int ok = 1;
    if (i < n_vox) {
        int lo = counts_raw[2 * i];
        int hi = counts_raw[2 * i + 1];
        ok = (hi == 0) && (lo >= 0) && (lo <= 4);
    }
    unsigned all = __ballot_sync(0xFFFFFFFFu, ok);
    if (i == 0) g_counts_are_i64 = (all == 0xFFFFFFFFu) ? 1 : 0;
}

// 8 threads per voxel. Thread (t & 7) computes output channels [4*(t&7), +4)
// and stores one float4 -> warp stores 512B contiguous (4 voxels * 128B).
__global__ __launch_bounds__(256, 8)
void radar_pointnet_kernel(const float4* __restrict__ vf,     // [V*P] float4 (C_IN=4)
                           const float4* __restrict__ Wg,     // [32] float4 rows
                           const int*    __restrict__ counts_raw,
                           float4* __restrict__ out,          // [V*8] float4 (C_OUT=32)
                           int n_vox)
{
    __shared__ float4 sW[32];
    if (threadIdx.x < 32) sW[threadIdx.x] = Wg[threadIdx.x];
    __syncthreads();

    long long t = (long long)blockIdx.x * blockDim.x + threadIdx.x;
    long long v = t >> 3;
    if (v >= n_vox) return;
    int lane8 = (int)t & 7;

    // Load this voxel's 4 points (redundant across the 8 threads of the voxel;
    // intra-line broadcast, warp covers 4 voxels * 64B contiguous per step).
    const float4* p = vf + (v << 2);
    float4 q0 = p[0], q1 = p[1], q2 = p[2], q3 = p[3];

    // Channel-wise sum over points.
    float sx = (q0.x + q1.x) + (q2.x + q3.x);
    float sy = (q0.y + q1.y) + (q2.y + q3.y);
    float sz = (q0.z + q1.z) + (q2.z + q3.z);
    float sw = (q0.w + q1.w) + (q2.w + q3.w);

    // Normalizer (dtype decided by probe; uniform branch, flag is L2-resident).
    int cnt;
    if (g_counts_are_i64) cnt = counts_raw[v << 1];   // low 32 bits of int64
    else                  cnt = counts_raw[v];
    float inv = 1.0f / (float)(cnt > 1 ? cnt : 1);
    sx *= inv; sy *= inv; sz *= inv; sw *= inv;

    // 4 output channels = 4 dot products with W rows.
    int o = lane8 << 2;
    float4 w0 = sW[o + 0], w1 = sW[o + 1], w2 = sW[o + 2], w3 = sW[o + 3];
    float4 r;
    r.x = sx * w0.x + sy * w0.y + sz * w0.z + sw * w0.w;
    r.y = sx * w1.x + sy * w1.y + sz * w1.z + sw * w1.w;
    r.z = sx * w2.x + sy * w2.y + sz * w2.z + sw * w2.w;
    r.w = sx * w3.x + sy * w3.y + sz * w3.z + sw * w3.w;

    out[(v << 3) + lane8] = r;   // warp-contiguous 512B
}

extern "C" void kernel_launch(void* const* d_in, const int* in_sizes, int n_in,
                              void* d_out, int out_size)
{
    const float4* vf     = (const float4*)d_in[0];   // [V, P, C_IN] f32
    const float4* W      = (const float4*)d_in[1];   // [32, 4] f32
    const int*    counts = (const int*)d_in[2];      // int64 or int32, probed
    float4*       out    = (float4*)d_out;           // [V, 32] f32
    int n_vox = in_sizes[2];
    if (n_vox <= 0) return;

    probe_dtype_kernel<<<1, 32>>>(counts, n_vox);

    long long threads = 8LL * n_vox;
    int block = 256;
    long long grid = (threads + block - 1) / block;
    radar_pointnet_kernel<<<(unsigned)grid, block>>>(vf, W, counts, out, n_vox);
}

// round 3
// speedup vs baseline: 1.1225x; 1.1225x over previous
#include <cuda_runtime.h>
#include <cstdint>

// Flag: 1 if voxel_num_points is int64 (LE, low word holds value), 0 if int32.
__device__ int g_counts_are_i64;

__global__ void probe_dtype_kernel(const int* __restrict__ counts_raw, int n_vox)
{
    int i = threadIdx.x;               // 0..31
    int ok = 1;
    if (i < n_vox) {
        int lo = counts_raw[2 * i];
        int hi = counts_raw[2 * i + 1];
        ok = (hi == 0) && (lo >= 0) && (lo <= 4);
    }
    unsigned all = __ballot_sync(0xFFFFFFFFu, ok);
    if (i == 0) g_counts_are_i64 = (all == 0xFFFFFFFFu) ? 1 : 0;
}

// Warp processes 8 voxels per iteration.
//   Load phase : lane = (voxel g 0..7, point 0..3) -> 1 dense LDG.128 (512B/warp).
//   Reduce     : butterfly xor1,xor2 within 4-lane groups (sum over points).
//   Scale      : multiply by 1/max(cnt,1) (count of own voxel).
//   Remap      : 1 shuffle round so lane l holds sums of voxels l>>3 and l>>3+4.
//   Store phase: 2 dense STG.128 (512B each) covering 8 voxels x 128B output.
// W rows are preloaded to registers once per thread; grid-stride loop amortizes.
__global__ __launch_bounds__(256, 8)
void radar_pointnet_kernel(const float4* __restrict__ vf,     // [V*4] float4
                           const float4* __restrict__ Wg,     // [32] float4 rows
                           const int*    __restrict__ counts_raw,
                           float4* __restrict__ out,          // [V*8] float4
                           int n_vox)
{
    const int lane = threadIdx.x & 31;
    const int col  = lane & 7;          // output float4 column this lane stores
    const int vg   = lane >> 2;         // voxel-in-group for load/reduce phase
    const int pt   = lane & 3;          // point index for load phase
    const int srcA = (lane >> 3) << 2;  // lane holding voxel (l>>3)'s sum
    const int srcB = srcA + 16;         // lane holding voxel (l>>3)+4's sum
    const bool i64 = (g_counts_are_i64 != 0);

    // W rows for channels [4*col, 4*col+4): registers, loaded once.
    const float4 w0 = Wg[col * 4 + 0];
    const float4 w1 = Wg[col * 4 + 1];
    const float4 w2 = Wg[col * 4 + 2];
    const float4 w3 = Wg[col * 4 + 3];

    const long long groups  = ((long long)n_vox + 7) >> 3;
    const long long warp_id = ((long long)blockIdx.x * blockDim.x + threadIdx.x) >> 5;
    const long long nwarps  = ((long long)gridDim.x * blockDim.x) >> 5;

    for (long long g = warp_id; g < groups; g += nwarps) {
        const long long vbase = g << 3;
        const long long v     = vbase + vg;

        float4 q = make_float4(0.f, 0.f, 0.f, 0.f);
        int cnt = 1;
        if (v < n_vox) {
            q   = vf[(v << 2) + pt];                       // dense 512B/warp
            cnt = i64 ? counts_raw[v << 1] : counts_raw[v];
        }

        // Sum over the 4 points of each voxel (4-lane butterfly).
        q.x += __shfl_xor_sync(0xFFFFFFFFu, q.x, 1);
        q.y += __shfl_xor_sync(0xFFFFFFFFu, q.y, 1);
        q.z += __shfl_xor_sync(0xFFFFFFFFu, q.z, 1);
        q.w += __shfl_xor_sync(0xFFFFFFFFu, q.w, 1);
        q.x += __shfl_xor_sync(0xFFFFFFFFu, q.x, 2);
        q.y += __shfl_xor_sync(0xFFFFFFFFu, q.y, 2);
        q.z += __shfl_xor_sync(0xFFFFFFFFu, q.z, 2);
        q.w += __shfl_xor_sync(0xFFFFFFFFu, q.w, 2);

        const float inv = 1.0f / (float)(cnt > 1 ? cnt : 1);
        q.x *= inv; q.y *= inv; q.z *= inv; q.w *= inv;

        // Redistribute scaled sums for dense stores.
        const float ax = __shfl_sync(0xFFFFFFFFu, q.x, srcA);
        const float ay = __shfl_sync(0xFFFFFFFFu, q.y, srcA);
        const float az = __shfl_sync(0xFFFFFFFFu, q.z, srcA);
        const float aw = __shfl_sync(0xFFFFFFFFu, q.w, srcA);
        const float bx = __shfl_sync(0xFFFFFFFFu, q.x, srcB);
        const float by = __shfl_sync(0xFFFFFFFFu, q.y, srcB);
        const float bz = __shfl_sync(0xFFFFFFFFu, q.z, srcB);
        const float bw = __shfl_sync(0xFFFFFFFFu, q.w, srcB);

        float4 rA, rB;
        rA.x = ax * w0.x + ay * w0.y + az * w0.z + aw * w0.w;
        rA.y = ax * w1.x + ay * w1.y + az * w1.z + aw * w1.w;
        rA.z = ax * w2.x + ay * w2.y + az * w2.z + aw * w2.w;
        rA.w = ax * w3.x + ay * w3.y + az * w3.z + aw * w3.w;
        rB.x = bx * w0.x + by * w0.y + bz * w0.z + bw * w0.w;
        rB.y = bx * w1.x + by * w1.y + bz * w1.z + bw * w1.w;
        rB.z = bx * w2.x + by * w2.y + bz * w2.z + bw * w2.w;
        rB.w = bx * w3.x + by * w3.y + bz * w3.z + bw * w3.w;

        const long long vA = vbase + (lane >> 3);
        if (vA < n_vox)     out[(vbase << 3) + lane]      = rA;  // voxels 0..3, dense 512B
        if (vA + 4 < n_vox) out[(vbase << 3) + 32 + lane] = rB;  // voxels 4..7, dense 512B
    }
}

extern "C" void kernel_launch(void* const* d_in, const int* in_sizes, int n_in,
                              void* d_out, int out_size)
{
    const float4* vf     = (const float4*)d_in[0];
    const float4* W      = (const float4*)d_in[1];
    const int*    counts = (const int*)d_in[2];
    float4*       out    = (float4*)d_out;
    int n_vox = in_sizes[2];
    if (n_vox <= 0) return;

    probe_dtype_kernel<<<1, 32>>>(counts, n_vox);

    // Grid-stride: fill the chip (148 SMs x 8 blocks of 256), amortize W preload.
    int block = 256;
    long long groups = ((long long)n_vox + 7) >> 3;
    long long max_blocks = (groups * 32 + block - 1) / block;  // at most 1 group/warp
    int grid = (int)((max_blocks < 1184) ? max_blocks : 1184);
    radar_pointnet_kernel<<<grid, block>>>(vf, W, counts, out, n_vox);
}

// round 5
// speedup vs baseline: 1.9408x; 1.7290x over previous
#include <cuda_runtime.h>
#include <cstdint>

// Flag: 1 if voxel_num_points is int64 (LE, low word holds value), 0 if int32.
__device__ int g_counts_are_i64;

__global__ void probe_dtype_kernel(const int* __restrict__ counts_raw, int n_vox)
{
    int i = threadIdx.x;               // 0..31
    int ok = 1;
    if (i < n_vox) {
        int lo = counts_raw[2 * i];
        int hi = counts_raw[2 * i + 1];
        ok = (hi == 0) && (lo >= 0) && (lo <= 4);
    }
    unsigned all = __ballot_sync(0xFFFFFFFFu, ok);
    if (i == 0) g_counts_are_i64 = (all == 0xFFFFFFFFu) ? 1 : 0;
}

// Warp processes 16 voxels per iteration.
//   Load  : lane l takes voxel v = vbase + (l>>1), points 2*(l&1), 2*(l&1)+1
//           -> two LDG.128 (jointly dense 1024B), local add, ONE xor-1 butterfly.
//   Scale : 1/max(cnt,1) applied to the sum.
//   Remap : even lanes STS the 16 voxel sums (256B dense); broadcast LDS per
//           store round (no shuffles).
//   Store : 4 rounds of dense STG.128 (512B each) = 16 voxels x 128B output.
// W rows live in registers (lane's 4 output channels), amortized by grid-stride.
__global__ __launch_bounds__(256, 8)
void radar_pointnet_kernel(const float4* __restrict__ vf,     // [V*4] float4
                           const float4* __restrict__ Wg,     // [32] float4 rows
                           const int*    __restrict__ counts_raw,
                           float4* __restrict__ out,          // [V*8] float4
                           int n_vox)
{
    __shared__ float4 sSum[8][16];      // [warp][voxel-in-group]

    const int lane = threadIdx.x & 31;
    const int wrp  = threadIdx.x >> 5;
    const int col  = lane & 7;          // this lane's output float4 column
    const int vloc = lane >> 1;         // voxel-in-group this lane loads (0..15)
    const int vsel = lane >> 3;         // voxel-in-quad for store rounds (0..3)
    const bool i64 = (g_counts_are_i64 != 0);

    // W rows for channels [4*col, 4*col+4): registers, loaded once.
    const float4 w0 = Wg[col * 4 + 0];
    const float4 w1 = Wg[col * 4 + 1];
    const float4 w2 = Wg[col * 4 + 2];
    const float4 w3 = Wg[col * 4 + 3];

    const long long groups  = ((long long)n_vox + 15) >> 4;
    const long long warp_id = ((long long)blockIdx.x * blockDim.x + threadIdx.x) >> 5;
    const long long nwarps  = ((long long)gridDim.x * blockDim.x) >> 5;

    for (long long g = warp_id; g < groups; g += nwarps) {
        const long long vbase = g << 4;
        const long long v     = vbase + vloc;

        float4 q0 = make_float4(0.f, 0.f, 0.f, 0.f);
        float4 q1 = q0;
        int cnt = 1;
        if (v < n_vox) {
            const float4* p = vf + (v << 2) + ((lane & 1) << 1);
            q0 = p[0];
            q1 = p[1];
            cnt = i64 ? counts_raw[v << 1] : counts_raw[v];
        }

        // Local pair-sum (FMA pipe), then one butterfly round with the partner
        // lane holding the other two points of the same voxel.
        float sx = q0.x + q1.x, sy = q0.y + q1.y;
        float sz = q0.z + q1.z, sw = q0.w + q1.w;
        sx += __shfl_xor_sync(0xFFFFFFFFu, sx, 1);
        sy += __shfl_xor_sync(0xFFFFFFFFu, sy, 1);
        sz += __shfl_xor_sync(0xFFFFFFFFu, sz, 1);
        sw += __shfl_xor_sync(0xFFFFFFFFu, sw, 1);

        const float inv = 1.0f / (float)(cnt > 1 ? cnt : 1);
        if ((lane & 1) == 0)
            sSum[wrp][vloc] = make_float4(sx * inv, sy * inv, sz * inv, sw * inv);
        __syncwarp();

        // 4 dense store rounds; round r covers voxels vbase + 4r .. +4r+3.
        #pragma unroll
        for (int r = 0; r < 4; r++) {
            const long long vr = vbase + r * 4 + vsel;
            if (vr < n_vox) {
                const float4 t = sSum[wrp][r * 4 + vsel];   // broadcast LDS
                float4 o;
                o.x = t.x * w0.x + t.y * w0.y + t.z * w0.z + t.w * w0.w;
                o.y = t.x * w1.x + t.y * w1.y + t.z * w1.z + t.w * w1.w;
                o.z = t.x * w2.x + t.y * w2.y + t.z * w2.z + t.w * w2.w;
                o.w = t.x * w3.x + t.y * w3.y + t.z * w3.z + t.w * w3.w;
                out[(vbase << 3) + r * 32 + lane] = o;      // dense 512B
            }
        }
        __syncwarp();   // protect sSum before next iteration's STS
    }
}

extern "C" void kernel_launch(void* const* d_in, const int* in_sizes, int n_in,
                              void* d_out, int out_size)
{
    const float4* vf     = (const float4*)d_in[0];
    const float4* W      = (const float4*)d_in[1];
    const int*    counts = (const int*)d_in[2];
    float4*       out    = (float4*)d_out;
    int n_vox = in_sizes[2];
    if (n_vox <= 0) return;

    probe_dtype_kernel<<<1, 32>>>(counts, n_vox);

    int block = 256;
    long long groups = ((long long)n_vox + 15) >> 4;
    long long max_blocks = (groups * 32 + block - 1) / block;  // at most 1 group/warp
    int grid = (int)((max_blocks < 1184) ? max_blocks : 1184);
    radar_pointnet_kernel<<<grid, block>>>(vf, W, counts, out, n_vox);
}

// round 6
// speedup vs baseline: 2.1112x; 1.0878x over previous
#include <cuda_runtime.h>
#include <cstdint>

// Warp processes 16 voxels per iteration.
//   Load  : lane l -> voxel v = vbase + (l>>1), points 2*(l&1), 2*(l&1)+1
//           (two LDG.128, jointly dense 1024B), local add, ONE xor-1 butterfly.
//   Scale : 1/max(cnt,1).
//   Remap : even lanes STS the 16 voxel sums (dense); broadcast LDS per round.
//   Store : 4 rounds of dense STG.128 (512B each) = 16 voxels x 128B output.
// Count dtype (int32 vs int64) probed in-kernel by warp 0 of each block.
// sSum double-buffered by iteration parity -> no trailing __syncwarp.
__global__ __launch_bounds__(256, 8)
void radar_pointnet_kernel(const float4* __restrict__ vf,     // [V*4] float4
                           const float4* __restrict__ Wg,     // [32] float4 rows
                           const int*    __restrict__ counts_raw,
                           float4* __restrict__ out,          // [V*8] float4
                           int n_vox)
{
    __shared__ float4 sSum[8][2][16];   // [warp][parity][voxel-in-group]
    __shared__ int    sI64;

    // ---- In-block dtype probe (warp 0): int64 pairs must look like (0..4, 0).
    if (threadIdx.x < 32) {
        int i = threadIdx.x;
        int ok = 1;
        if (2 * i + 1 < n_vox) {        // safe under the int32 interpretation too
            int lo = counts_raw[2 * i];
            int hi = counts_raw[2 * i + 1];
            ok = (hi == 0) && (lo >= 0) && (lo <= 4);
        }
        unsigned all = __ballot_sync(0xFFFFFFFFu, ok);
        if (i == 0) sI64 = (all == 0xFFFFFFFFu) ? 1 : 0;
    }
    __syncthreads();
    const bool i64 = (sI64 != 0);

    const int lane = threadIdx.x & 31;
    const int wrp  = threadIdx.x >> 5;
    const int col  = lane & 7;          // this lane's output float4 column
    const int vloc = lane >> 1;         // voxel-in-group this lane loads (0..15)
    const int vsel = lane >> 3;         // voxel-in-quad for store rounds (0..3)

    // W rows for channels [4*col, 4*col+4): registers, loaded once.
    const float4 w0 = Wg[col * 4 + 0];
    const float4 w1 = Wg[col * 4 + 1];
    const float4 w2 = Wg[col * 4 + 2];
    const float4 w3 = Wg[col * 4 + 3];

    const int groups  = (n_vox + 15) >> 4;
    const int warp_id = (blockIdx.x * blockDim.x + threadIdx.x) >> 5;
    const int nwarps  = (gridDim.x * blockDim.x) >> 5;

    int buf = 0;
    for (int g = warp_id; g < groups; g += nwarps, buf ^= 1) {
        const int vbase = g << 4;
        const int v     = vbase + vloc;
        const bool full = (vbase + 16 <= n_vox);

        float4 q0, q1;
        int cnt;
        if (full | (v < n_vox)) {
            const float4* p = vf + (v << 2) + ((lane & 1) << 1);
            q0  = p[0];
            q1  = p[1];
            cnt = i64 ? counts_raw[v << 1] : counts_raw[v];
        } else {
            q0 = q1 = make_float4(0.f, 0.f, 0.f, 0.f);
            cnt = 1;
        }

        // Pair-sum locally (FMA pipe), then one butterfly with the partner lane.
        float sx = q0.x + q1.x, sy = q0.y + q1.y;
        float sz = q0.z + q1.z, sw = q0.w + q1.w;
        sx += __shfl_xor_sync(0xFFFFFFFFu, sx, 1);
        sy += __shfl_xor_sync(0xFFFFFFFFu, sy, 1);
        sz += __shfl_xor_sync(0xFFFFFFFFu, sz, 1);
        sw += __shfl_xor_sync(0xFFFFFFFFu, sw, 1);

        const float inv = 1.0f / (float)(cnt > 1 ? cnt : 1);
        if ((lane & 1) == 0)
            sSum[wrp][buf][vloc] = make_float4(sx * inv, sy * inv, sz * inv, sw * inv);
        __syncwarp();

        if (full) {
            #pragma unroll
            for (int r = 0; r < 4; r++) {
                const float4 t = sSum[wrp][buf][r * 4 + vsel];   // broadcast LDS
                float4 o;
                o.x = t.x * w0.x + t.y * w0.y + t.z * w0.z + t.w * w0.w;
                o.y = t.x * w1.x + t.y * w1.y + t.z * w1.z + t.w * w1.w;
                o.z = t.x * w2.x + t.y * w2.y + t.z * w2.z + t.w * w2.w;
                o.w = t.x * w3.x + t.y * w3.y + t.z * w3.z + t.w * w3.w;
                out[(vbase << 3) + r * 32 + lane] = o;           // dense 512B
            }
        } else {
            #pragma unroll
            for (int r = 0; r < 4; r++) {
                if (vbase + r * 4 + vsel < n_vox) {
                    const float4 t = sSum[wrp][buf][r * 4 + vsel];
                    float4 o;
                    o.x = t.x * w0.x + t.y * w0.y + t.z * w0.z + t.w * w0.w;
                    o.y = t.x * w1.x + t.y * w1.y + t.z * w1.z + t.w * w1.w;
                    o.z = t.x * w2.x + t.y * w2.y + t.z * w2.z + t.w * w2.w;
                    o.w = t.x * w3.x + t.y * w3.y + t.z * w3.z + t.w * w3.w;
                    out[(vbase << 3) + r * 32 + lane] = o;
                }
            }
        }
        // No trailing syncwarp: next iteration writes the other sSum buffer;
        // reuse of this buffer two iterations out is ordered by the next
        // iteration's mid-loop __syncwarp.
    }
}

extern "C" void kernel_launch(void* const* d_in, const int* in_sizes, int n_in,
                              void* d_out, int out_size)
{
    const float4* vf     = (const float4*)d_in[0];
    const float4* W      = (const float4*)d_in[1];
    const int*    counts = (const int*)d_in[2];
    float4*       out    = (float4*)d_out;
    int n_vox = in_sizes[2];
    if (n_vox <= 0) return;

    int block = 256;
    long long groups = ((long long)n_vox + 15) >> 4;
    long long max_blocks = (groups * 32 + block - 1) / block;  // at most 1 group/warp
    int grid = (int)((max_blocks < 1184) ? max_blocks : 1184);
    radar_pointnet_kernel<<<grid, block>>>(vf, W, counts, out, n_vox);
}

// round 7
// speedup vs baseline: 2.1252x; 1.0066x over previous
#include <cuda_runtime.h>
#include <cstdint>

// Warp processes 16 voxels per group; grid-stride loop is software-pipelined
// (next group's loads issued before current group's reduce/store phase).
//   Load  : lane l -> voxel v = vbase + (l>>1), points 2*(l&1), 2*(l&1)+1
//           (two LDG.128, jointly dense 1024B), local add, ONE xor-1 butterfly.
//   Scale : 1/max(cnt,1).
//   Remap : even lanes STS the 16 voxel sums; broadcast LDS per store round.
//   Store : 4 rounds of dense STG.128 (512B each) with __stcs (evict-first,
//           keeps the 72MB feature+count working set L2-resident across
//           graph replays; output is never re-read).
// Count dtype (int32 vs int64) probed in-kernel by warp 0 of each block.
__global__ __launch_bounds__(256, 6)
void radar_pointnet_kernel(const float4* __restrict__ vf,     // [V*4] float4
                           const float4* __restrict__ Wg,     // [32] float4 rows
                           const int*    __restrict__ counts_raw,
                           float4* __restrict__ out,          // [V*8] float4
                           int n_vox)
{
    __shared__ float4 sSum[8][2][16];   // [warp][parity][voxel-in-group]
    __shared__ int    sI64;

    // ---- In-block dtype probe (warp 0): int64 pairs must look like (0..4, 0).
    if (threadIdx.x < 32) {
        int i = threadIdx.x;
        int ok = 1;
        if (2 * i + 1 < n_vox) {        // safe under the int32 interpretation too
            int lo = counts_raw[2 * i];
            int hi = counts_raw[2 * i + 1];
            ok = (hi == 0) && (lo >= 0) && (lo <= 4);
        }
        unsigned all = __ballot_sync(0xFFFFFFFFu, ok);
        if (i == 0) sI64 = (all == 0xFFFFFFFFu) ? 1 : 0;
    }
    __syncthreads();
    const bool i64 = (sI64 != 0);

    const int lane = threadIdx.x & 31;
    const int wrp  = threadIdx.x >> 5;
    const int col  = lane & 7;          // this lane's output float4 column
    const int vloc = lane >> 1;         // voxel-in-group this lane loads (0..15)
    const int vsel = lane >> 3;         // voxel-in-quad for store rounds (0..3)

    // W rows for channels [4*col, 4*col+4): registers, loaded once.
    const float4 w0 = Wg[col * 4 + 0];
    const float4 w1 = Wg[col * 4 + 1];
    const float4 w2 = Wg[col * 4 + 2];
    const float4 w3 = Wg[col * 4 + 3];

    const int groups  = (n_vox + 15) >> 4;
    const int warp_id = (blockIdx.x * blockDim.x + threadIdx.x) >> 5;
    const int nwarps  = (gridDim.x * blockDim.x) >> 5;

    // ---- Pipeline prologue: load group warp_id.
    int g = warp_id;
    float4 q0 = make_float4(0.f, 0.f, 0.f, 0.f), q1 = q0;
    int cnt = 1;
    if (g < groups) {
        const int v = (g << 4) + vloc;
        if (v < n_vox) {
            const float4* p = vf + (v << 2) + ((lane & 1) << 1);
            q0  = p[0];
            q1  = p[1];
            cnt = i64 ? counts_raw[v << 1] : counts_raw[v];
        }
    }

    int buf = 0;
    while (g < groups) {
        // ---- Prefetch next group (overlaps with this group's compute/stores).
        const int gn = g + nwarps;
        float4 n0 = make_float4(0.f, 0.f, 0.f, 0.f), n1 = n0;
        int ncnt = 1;
        if (gn < groups) {
            const int vn = (gn << 4) + vloc;
            if (vn < n_vox) {
                const float4* p = vf + (vn << 2) + ((lane & 1) << 1);
                n0   = p[0];
                n1   = p[1];
                ncnt = i64 ? counts_raw[vn << 1] : counts_raw[vn];
            }
        }

        // ---- Reduce current group: local pair-sum + one xor-1 butterfly.
        float sx = q0.x + q1.x, sy = q0.y + q1.y;
        float sz = q0.z + q1.z, sw = q0.w + q1.w;
        sx += __shfl_xor_sync(0xFFFFFFFFu, sx, 1);
        sy += __shfl_xor_sync(0xFFFFFFFFu, sy, 1);
        sz += __shfl_xor_sync(0xFFFFFFFFu, sz, 1);
        sw += __shfl_xor_sync(0xFFFFFFFFu, sw, 1);

        const float inv = 1.0f / (float)(cnt > 1 ? cnt : 1);
        if ((lane & 1) == 0)
            sSum[wrp][buf][vloc] = make_float4(sx * inv, sy * inv, sz * inv, sw * inv);
        __syncwarp();

        const int vbase = g << 4;
        const bool full = (vbase + 16 <= n_vox);
        #pragma unroll
        for (int r = 0; r < 4; r++) {
            if (full || (vbase + r * 4 + vsel < n_vox)) {
                const float4 t = sSum[wrp][buf][r * 4 + vsel];   // broadcast LDS
                float4 o;
                o.x = t.x * w0.x + t.y * w0.y + t.z * w0.z + t.w * w0.w;
                o.y = t.x * w1.x + t.y * w1.y + t.z * w1.z + t.w * w1.w;
                o.z = t.x * w2.x + t.y * w2.y + t.z * w2.z + t.w * w2.w;
                o.w = t.x * w3.x + t.y * w3.y + t.z * w3.z + t.w * w3.w;
                __stcs(&out[(vbase << 3) + r * 32 + lane], o);   // dense 512B, evict-first
            }
        }

        // ---- Rotate pipeline.
        q0 = n0; q1 = n1; cnt = ncnt;
        g = gn;
        buf ^= 1;
        // No trailing syncwarp: next iteration writes the other sSum buffer;
        // reuse two iterations out is ordered by the next mid-loop __syncwarp.
    }
}

extern "C" void kernel_launch(void* const* d_in, const int* in_sizes, int n_in,
                              void* d_out, int out_size)
{
    const float4* vf     = (const float4*)d_in[0];
    const float4* W      = (const float4*)d_in[1];
    const int*    counts = (const int*)d_in[2];
    float4*       out    = (float4*)d_out;
    int n_vox = in_sizes[2];
    if (n_vox <= 0) return;

    int block = 256;
    long long groups = ((long long)n_vox + 15) >> 4;
    long long max_blocks = (groups * 32 + block - 1) / block;  // at most 1 group/warp
    int grid = (int)((max_blocks < 888) ? max_blocks : 888);   // 148 SMs x 6 blocks
    radar_pointnet_kernel<<<grid, block>>>(vf, W, counts, out, n_vox);
}

// round 9
// speedup vs baseline: 2.2269x; 1.0478x over previous
#include <cuda_runtime.h>
#include <cstdint>

// Warp processes 16 voxels per iteration (R6 structure, occ 8).
//   Load  : lane l -> voxel v = vbase + (l>>1), points 2*(l&1), 2*(l&1)+1
//           (two LDG.128, jointly covering 1024B), local add, ONE xor-1 butterfly.
//   Scale : 1/max(cnt,1).
//   Remap : even lanes STS the 16 voxel sums; broadcast LDS per store round.
//   Store : 4 rounds of dense STG.128 (512B each) via __stcs (evict-first:
//           keeps the 72MB feature+count set L2-resident across graph replays;
//           output is never re-read).
// Count dtype (int32 vs int64) probed in-kernel by warp 0 of each block;
// published as an index SHIFT (0 or 1) so the hot loop has no select.
__global__ __launch_bounds__(256, 8)
void radar_pointnet_kernel(const float4* __restrict__ vf,     // [V*4] float4
                           const float4* __restrict__ Wg,     // [32] float4 rows
                           const int*    __restrict__ counts_raw,
                           float4* __restrict__ out,          // [V*8] float4
                           int n_vox)
{
    __shared__ float4 sSum[8][2][16];   // [warp][parity][voxel-in-group]
    __shared__ int    sShift;

    // ---- In-block dtype probe (warp 0): int64 pairs must look like (0..4, 0).
    if (threadIdx.x < 32) {
        int i = threadIdx.x;
        int ok = 1;
        if (2 * i + 1 < n_vox) {        // safe under the int32 interpretation too
            int lo = counts_raw[2 * i];
            int hi = counts_raw[2 * i + 1];
            ok = (hi == 0) && (lo >= 0) && (lo <= 4);
        }
        unsigned all = __ballot_sync(0xFFFFFFFFu, ok);
        if (i == 0) sShift = (all == 0xFFFFFFFFu) ? 1 : 0;
    }
    __syncthreads();
    const int cshift = sShift;

    const int lane = threadIdx.x & 31;
    const int wrp  = threadIdx.x >> 5;
    const int col  = lane & 7;          // this lane's output float4 column
    const int vloc = lane >> 1;         // voxel-in-group this lane loads (0..15)
    const int vsel = lane >> 3;         // voxel-in-quad for store rounds (0..3)

    // W rows for channels [4*col, 4*col+4): registers, loaded once.
    const float4 w0 = Wg[col * 4 + 0];
    const float4 w1 = Wg[col * 4 + 1];
    const float4 w2 = Wg[col * 4 + 2];
    const float4 w3 = Wg[col * 4 + 3];

    const int groups  = (n_vox + 15) >> 4;
    const int warp_id = (blockIdx.x * blockDim.x + threadIdx.x) >> 5;
    const int nwarps  = (gridDim.x * blockDim.x) >> 5;

    int buf = 0;
    for (int g = warp_id; g < groups; g += nwarps, buf ^= 1) {
        const int vbase = g << 4;
        const int v     = vbase + vloc;
        const bool full = (vbase + 16 <= n_vox);

        float4 q0, q1;
        int cnt;
        if (full | (v < n_vox)) {
            const float4* p = vf + (v << 2) + ((lane & 1) << 1);
            q0  = p[0];
            q1  = p[1];
            cnt = counts_raw[v << cshift];
        } else {
            q0 = q1 = make_float4(0.f, 0.f, 0.f, 0.f);
            cnt = 1;
        }

        // Pair-sum locally (FMA pipe), then one butterfly with the partner lane.
        float sx = q0.x + q1.x, sy = q0.y + q1.y;
        float sz = q0.z + q1.z, sw = q0.w + q1.w;
        sx += __shfl_xor_sync(0xFFFFFFFFu, sx, 1);
        sy += __shfl_xor_sync(0xFFFFFFFFu, sy, 1);
        sz += __shfl_xor_sync(0xFFFFFFFFu, sz, 1);
        sw += __shfl_xor_sync(0xFFFFFFFFu, sw, 1);

        const float inv = 1.0f / (float)(cnt > 1 ? cnt : 1);
        if ((lane & 1) == 0)
            sSum[wrp][buf][vloc] = make_float4(sx * inv, sy * inv, sz * inv, sw * inv);
        __syncwarp();

        if (full) {
            #pragma unroll
            for (int r = 0; r < 4; r++) {
                const float4 t = sSum[wrp][buf][r * 4 + vsel];   // broadcast LDS
                float4 o;
                o.x = t.x * w0.x + t.y * w0.y + t.z * w0.z + t.w * w0.w;
                o.y = t.x * w1.x + t.y * w1.y + t.z * w1.z + t.w * w1.w;
                o.z = t.x * w2.x + t.y * w2.y + t.z * w2.z + t.w * w2.w;
                o.w = t.x * w3.x + t.y * w3.y + t.z * w3.z + t.w * w3.w;
                __stcs(&out[(vbase << 3) + r * 32 + lane], o);   // dense 512B, evict-first
            }
        } else {
            #pragma unroll
            for (int r = 0; r < 4; r++) {
                if (vbase + r * 4 + vsel < n_vox) {
                    const float4 t = sSum[wrp][buf][r * 4 + vsel];
                    float4 o;
                    o.x = t.x * w0.x + t.y * w0.y + t.z * w0.z + t.w * w0.w;
                    o.y = t.x * w1.x + t.y * w1.y + t.z * w1.z + t.w * w1.w;
                    o.z = t.x * w2.x + t.y * w2.y + t.z * w2.z + t.w * w2.w;
                    o.w = t.x * w3.x + t.y * w3.y + t.z * w3.z + t.w * w3.w;
                    __stcs(&out[(vbase << 3) + r * 32 + lane], o);
                }
            }
        }
        // No trailing syncwarp: next iteration writes the other sSum buffer;
        // reuse two iterations out is ordered by the next mid-loop __syncwarp.
    }
}

extern "C" void kernel_launch(void* const* d_in, const int* in_sizes, int n_in,
                              void* d_out, int out_size)
{
    const float4* vf     = (const float4*)d_in[0];
    const float4* W      = (const float4*)d_in[1];
    const int*    counts = (const int*)d_in[2];
    float4*       out    = (float4*)d_out;
    int n_vox = in_sizes[2];
    if (n_vox <= 0) return;

    int block = 256;
    long long groups = ((long long)n_vox + 15) >> 4;
    long long max_blocks = (groups * 32 + block - 1) / block;  // at most 1 group/warp
    int grid = (int)((max_blocks < 1184) ? max_blocks : 1184); // 148 SMs x 8 blocks
    radar_pointnet_kernel<<<grid, block>>>(vf, W, counts, out, n_vox);
}